// round 11
// baseline (speedup 1.0000x reference)
#include <cuda_runtime.h>
#include <cuda_bf16.h>

// IoU_31336081391713: elementwise YOLO IoU.
// Inputs: cell_nos [N,2] i32, output [N,5,5] f32, target [N,5] f32 -> IoU [N,5] f32.
// R10: TILE=288 (9 warps/block), cp.async 2-stage, direct register->gmem stores.
// 3 blocks/SM -> 27 warps/SM, 110KB reads in flight, fewest barriers per box.

#define YI 20.0f
#define TILE 288          // boxes per tile == threads per block
#define THREADS 288
#define NA 5
#define OUT_F (TILE * 25) // 7200 floats (28800 B, 1800 f4)
#define TGT_F (TILE * 5)  // 1440 floats (5760 B, 360 f4)
#define CELL_I (TILE * 2) // 576 ints   (2304 B, 144 i4)

#define STAGE_B (OUT_F * 4 + TGT_F * 4 + CELL_I * 4)  // 36864 B
#define OFF_TGT (OUT_F * 4)
#define OFF_CEL (OUT_F * 4 + TGT_F * 4)
#define SMEM_BYTES (2 * STAGE_B)                      // 73728 B

__device__ __forceinline__ void cpa16(void* smem, const void* gmem) {
    unsigned s = (unsigned)__cvta_generic_to_shared(smem);
    asm volatile("cp.async.cg.shared.global [%0], [%1], 16;\n" :: "r"(s), "l"(gmem));
}
#define CP_COMMIT() asm volatile("cp.async.commit_group;\n" ::: "memory")
#define CP_WAIT1()  asm volatile("cp.async.wait_group 1;\n" ::: "memory")

__device__ __forceinline__ void prefetch_tile(
    char* stage_base, int tid, size_t b0, int nb,
    const int* __restrict__ g_cell,
    const float* __restrict__ g_out,
    const float* __restrict__ g_tgt)
{
    float* s_out = (float*)stage_base;
    float* s_tgt = (float*)(stage_base + OFF_TGT);
    int*   s_cel = (int*)  (stage_base + OFF_CEL);
    if (nb == TILE) {
        const float4* go4 = reinterpret_cast<const float4*>(g_out + b0 * 25);
        #pragma unroll
        for (int i = tid; i < OUT_F / 4; i += THREADS) cpa16(&s_out[i * 4], go4 + i);
        const float4* gt4 = reinterpret_cast<const float4*>(g_tgt + b0 * 5);
        #pragma unroll
        for (int i = tid; i < TGT_F / 4; i += THREADS) cpa16(&s_tgt[i * 4], gt4 + i);
        const int4* gc4 = reinterpret_cast<const int4*>(g_cell + b0 * 2);
        if (tid < CELL_I / 4) cpa16(&s_cel[tid * 4], gc4 + tid);
    } else {
        // guarded scalar tail (last tile only)
        for (int i = tid; i < nb * 25; i += THREADS) s_out[i] = g_out[b0 * 25 + i];
        for (int i = tid; i < nb * 5;  i += THREADS) s_tgt[i] = g_tgt[b0 * 5 + i];
        for (int i = tid; i < nb * 2;  i += THREADS) s_cel[i] = g_cell[b0 * 2 + i];
    }
}

__global__ __launch_bounds__(THREADS) void iou_kernel(
    const int*   __restrict__ g_cell,
    const float* __restrict__ g_out,
    const float* __restrict__ g_tgt,
    float*       __restrict__ g_res,
    int n_boxes, int n_tiles)
{
    extern __shared__ char base[];

    const int tid = threadIdx.x;
    const int G   = gridDim.x;

    // prologue: stage first tile into stage 0
    {
        const int it = blockIdx.x;
        if (it < n_tiles) {
            const size_t b0 = (size_t)it * TILE;
            int nb = n_boxes - (int)b0; if (nb > TILE) nb = TILE;
            prefetch_tile(base, tid, b0, nb, g_cell, g_out, g_tgt);
        }
    }
    CP_COMMIT();

    int st = 0;
    for (int it = blockIdx.x; it < n_tiles; it += G, st ^= 1) {
        // stage next tile into the other stage (overlaps wait+compute+store)
        const int nt = it + G;
        if (nt < n_tiles) {
            const size_t b0n = (size_t)nt * TILE;
            int nbn = n_boxes - (int)b0n; if (nbn > TILE) nbn = TILE;
            prefetch_tile(base + (st ^ 1) * STAGE_B, tid, b0n, nbn,
                          g_cell, g_out, g_tgt);
        }
        CP_COMMIT();
        CP_WAIT1();           // current stage's group is complete
        __syncthreads();      // bar1: cross-thread visibility of cp.async data

        const size_t b0 = (size_t)it * TILE;
        int nb = n_boxes - (int)b0; if (nb > TILE) nb = TILE;

        char* sb = base + st * STAGE_B;
        const float* s_out = (const float*)sb;
        const float* s_tgt = (const float*)(sb + OFF_TGT);
        const int*   s_cel = (const int*)  (sb + OFF_CEL);

        if (tid < nb) {
            const float ci = (float)s_cel[tid * 2 + 0] * YI + YI * 0.5f;
            const float cj = (float)s_cel[tid * 2 + 1] * YI + YI * 0.5f;

            const float* t = &s_tgt[tid * 5];
            const float hg  = t[3] * YI;
            const float wg  = t[4] * YI;
            const float xcg = ci + t[1] * YI;
            const float ycg = cj + t[2] * YI;
            const float gx1 = ycg - wg * 0.5f;
            const float gy1 = xcg - hg * 0.5f;
            const float gx2 = ycg + wg * 0.5f;
            const float gy2 = xcg + hg * 0.5f;
            const float area_g = (gx2 - gx1) * (gy2 - gy1);

            const float* o = &s_out[tid * 25];
            float* r = g_res + (b0 + tid) * 5;
            #pragma unroll
            for (int a = 0; a < NA; a++) {
                const float* p = o + a * 5;
                const float h  = p[3] * YI;
                const float w  = p[4] * YI;
                const float xc = ci + p[1] * YI;
                const float yc = cj + p[2] * YI;
                const float px1 = yc - w * 0.5f;
                const float py1 = xc - h * 0.5f;
                const float px2 = yc + w * 0.5f;
                const float py2 = xc + h * 0.5f;
                const float area_p = (px2 - px1) * (py2 - py1);

                const float ltx = fmaxf(px1, gx1);
                const float lty = fmaxf(py1, gy1);
                const float rbx = fminf(px2, gx2);
                const float rby = fminf(py2, gy2);
                const float wx  = fmaxf(rbx - ltx, 0.0f);
                const float wy  = fmaxf(rby - lty, 0.0f);
                const float inter = wx * wy;
                const float uni   = area_p + area_g - inter;
                __stcs(r + a, inter / uni);   // direct streaming store
            }
        }
        __syncthreads();      // bar2: compute-reads of this stage done before
                              // iter+2's prefetch overwrites it
    }
}

extern "C" void kernel_launch(void* const* d_in, const int* in_sizes, int n_in,
                              void* d_out, int out_size) {
    const int*   cell = (const int*)d_in[0];
    const float* outp = (const float*)d_in[1];
    const float* tgt  = (const float*)d_in[2];
    float*       res  = (float*)d_out;

    const int n_boxes = in_sizes[0] / 2;
    const int n_tiles = (n_boxes + TILE - 1) / TILE;

    cudaFuncSetAttribute(iou_kernel, cudaFuncAttributeMaxDynamicSharedMemorySize,
                         SMEM_BYTES);

    int grid = 152 * 3;               // persistent: 3 blocks/SM (72KB dyn smem each)
    if (grid > n_tiles) grid = n_tiles;
    iou_kernel<<<grid, THREADS, SMEM_BYTES>>>(cell, outp, tgt, res, n_boxes, n_tiles);
}

// round 15
// speedup vs baseline: 1.1275x; 1.1275x over previous
#include <cuda_runtime.h>
#include <cuda_bf16.h>

// IoU_31336081391713: elementwise YOLO IoU.
// Inputs: cell_nos [N,2] i32, output [N,5,5] f32, target [N,5] f32 -> IoU [N,5] f32.
// R12 = R11 resubmit (container infra failure): TILE=256 cp.async double-buffered
// persistent blocks; result write-back via one cp.async.bulk SMEM->GMEM DMA per
// tile with double-buffered s_res. Removes all per-thread STG traffic.

#define YI 20.0f
#define TILE 256          // boxes per tile == threads per block
#define THREADS 256
#define NA 5
#define OUT_F (TILE * 25) // 6400 floats (25600 B)
#define TGT_F (TILE * 5)  // 1280 floats (5120 B)
#define CELL_I (TILE * 2) // 512 ints   (2048 B)

// dynamic smem layout (bytes)
#define OFF_OUT0 0
#define OFF_OUT1 (OFF_OUT0 + OUT_F * 4)
#define OFF_TGT0 (OFF_OUT1 + OUT_F * 4)
#define OFF_TGT1 (OFF_TGT0 + TGT_F * 4)
#define OFF_CEL0 (OFF_TGT1 + TGT_F * 4)
#define OFF_CEL1 (OFF_CEL0 + CELL_I * 4)
#define OFF_RES0 (OFF_CEL1 + CELL_I * 4)
#define OFF_RES1 (OFF_RES0 + TGT_F * 4)
#define SMEM_BYTES (OFF_RES1 + TGT_F * 4)   // 75776 B -> 3 blocks/SM

__device__ __forceinline__ void cpa16(void* smem, const void* gmem) {
    unsigned s = (unsigned)__cvta_generic_to_shared(smem);
    asm volatile("cp.async.cg.shared.global [%0], [%1], 16;\n" :: "r"(s), "l"(gmem));
}
#define CP_COMMIT() asm volatile("cp.async.commit_group;\n" ::: "memory")
#define CP_WAIT1()  asm volatile("cp.async.wait_group 1;\n" ::: "memory")

__device__ __forceinline__ void bulk_store(void* gmem, const void* smem, unsigned bytes) {
    unsigned s = (unsigned)__cvta_generic_to_shared(smem);
    asm volatile("cp.async.bulk.global.shared::cta.bulk_group [%0], [%1], %2;\n"
                 :: "l"(gmem), "r"(s), "r"(bytes) : "memory");
}
#define BULK_COMMIT()     asm volatile("cp.async.bulk.commit_group;\n" ::: "memory")
#define BULK_WAIT_READ1() asm volatile("cp.async.bulk.wait_group.read 1;\n" ::: "memory")
#define BULK_WAIT0()      asm volatile("cp.async.bulk.wait_group 0;\n" ::: "memory")
#define FENCE_ASYNC()     asm volatile("fence.proxy.async.shared::cta;\n" ::: "memory")

__device__ __forceinline__ void prefetch_tile(
    char* base, int st, int tid, size_t b0, int nb,
    const int* __restrict__ g_cell,
    const float* __restrict__ g_out,
    const float* __restrict__ g_tgt)
{
    float* s_out = (float*)(base + (st ? OFF_OUT1 : OFF_OUT0));
    float* s_tgt = (float*)(base + (st ? OFF_TGT1 : OFF_TGT0));
    int*   s_cel = (int*)  (base + (st ? OFF_CEL1 : OFF_CEL0));
    if (nb == TILE) {
        const float4* go4 = reinterpret_cast<const float4*>(g_out + b0 * 25);
        #pragma unroll
        for (int i = tid; i < OUT_F / 4; i += THREADS) cpa16(&s_out[i * 4], go4 + i);
        const float4* gt4 = reinterpret_cast<const float4*>(g_tgt + b0 * 5);
        #pragma unroll
        for (int i = tid; i < TGT_F / 4; i += THREADS) cpa16(&s_tgt[i * 4], gt4 + i);
        const int4* gc4 = reinterpret_cast<const int4*>(g_cell + b0 * 2);
        if (tid < CELL_I / 4) cpa16(&s_cel[tid * 4], gc4 + tid);
    } else {
        // guarded scalar tail (not hit for N=4M; kept for generality)
        for (int i = tid; i < nb * 25; i += THREADS) s_out[i] = g_out[b0 * 25 + i];
        for (int i = tid; i < nb * 5;  i += THREADS) s_tgt[i] = g_tgt[b0 * 5 + i];
        for (int i = tid; i < nb * 2;  i += THREADS) s_cel[i] = g_cell[b0 * 2 + i];
    }
}

__global__ __launch_bounds__(THREADS) void iou_kernel(
    const int*   __restrict__ g_cell,
    const float* __restrict__ g_out,
    const float* __restrict__ g_tgt,
    float*       __restrict__ g_res,
    int n_boxes, int n_tiles)
{
    extern __shared__ char base[];

    const int tid = threadIdx.x;
    const int G   = gridDim.x;

    // prologue: stage first tile into buffer 0
    {
        const int it = blockIdx.x;
        if (it < n_tiles) {
            const size_t b0 = (size_t)it * TILE;
            int nb = n_boxes - (int)b0; if (nb > TILE) nb = TILE;
            prefetch_tile(base, 0, tid, b0, nb, g_cell, g_out, g_tgt);
        }
    }
    CP_COMMIT();

    int st = 0, rb = 0;
    for (int it = blockIdx.x; it < n_tiles; it += G, st ^= 1, rb ^= 1) {
        // stage next tile into the other buffer (overlaps wait+compute+store)
        const int nt = it + G;
        if (nt < n_tiles) {
            const size_t b0n = (size_t)nt * TILE;
            int nbn = n_boxes - (int)b0n; if (nbn > TILE) nbn = TILE;
            prefetch_tile(base, st ^ 1, tid, b0n, nbn, g_cell, g_out, g_tgt);
        }
        CP_COMMIT();
        CP_WAIT1();               // current stage's load group complete
        if (tid == 0) BULK_WAIT_READ1();  // s_res[rb] fully read by bulk engine
        __syncthreads();          // bar1: load visibility + s_res[rb] reuse safe

        const size_t b0 = (size_t)it * TILE;
        int nb = n_boxes - (int)b0; if (nb > TILE) nb = TILE;

        const float* s_out = (const float*)(base + (st ? OFF_OUT1 : OFF_OUT0));
        const float* s_tgt = (const float*)(base + (st ? OFF_TGT1 : OFF_TGT0));
        const int*   s_cel = (const int*)  (base + (st ? OFF_CEL1 : OFF_CEL0));
        float*       s_res = (float*)(base + (rb ? OFF_RES1 : OFF_RES0));

        if (tid < nb) {
            const float ci = (float)s_cel[tid * 2 + 0] * YI + YI * 0.5f;
            const float cj = (float)s_cel[tid * 2 + 1] * YI + YI * 0.5f;

            const float* t = &s_tgt[tid * 5];
            const float hg  = t[3] * YI;
            const float wg  = t[4] * YI;
            const float xcg = ci + t[1] * YI;
            const float ycg = cj + t[2] * YI;
            const float gx1 = ycg - wg * 0.5f;
            const float gy1 = xcg - hg * 0.5f;
            const float gx2 = ycg + wg * 0.5f;
            const float gy2 = xcg + hg * 0.5f;
            const float area_g = (gx2 - gx1) * (gy2 - gy1);

            const float* o = &s_out[tid * 25];
            #pragma unroll
            for (int a = 0; a < NA; a++) {
                const float* p = o + a * 5;
                const float h  = p[3] * YI;
                const float w  = p[4] * YI;
                const float xc = ci + p[1] * YI;
                const float yc = cj + p[2] * YI;
                const float px1 = yc - w * 0.5f;
                const float py1 = xc - h * 0.5f;
                const float px2 = yc + w * 0.5f;
                const float py2 = xc + h * 0.5f;
                const float area_p = (px2 - px1) * (py2 - py1);

                const float ltx = fmaxf(px1, gx1);
                const float lty = fmaxf(py1, gy1);
                const float rbx = fminf(px2, gx2);
                const float rby = fminf(py2, gy2);
                const float wx  = fmaxf(rbx - ltx, 0.0f);
                const float wy  = fmaxf(rby - lty, 0.0f);
                const float inter = wx * wy;
                const float uni   = area_p + area_g - inter;
                s_res[tid * 5 + a] = inter / uni;
            }
        }
        __syncthreads();          // bar2: s_res complete across the block

        if (nb == TILE) {
            if (tid == 0) {
                FENCE_ASYNC();    // order generic s_res writes into async proxy
                bulk_store(g_res + b0 * 5, s_res, (unsigned)(TILE * 5 * 4));
                BULK_COMMIT();
            }
        } else {
            // tail: scalar stores (size not guaranteed /16)
            for (int i = tid; i < nb * 5; i += THREADS) g_res[b0 * 5 + i] = s_res[i];
        }
    }

    if (tid == 0) BULK_WAIT0();   // all bulk stores globally complete before exit
}

extern "C" void kernel_launch(void* const* d_in, const int* in_sizes, int n_in,
                              void* d_out, int out_size) {
    const int*   cell = (const int*)d_in[0];
    const float* outp = (const float*)d_in[1];
    const float* tgt  = (const float*)d_in[2];
    float*       res  = (float*)d_out;

    const int n_boxes = in_sizes[0] / 2;
    const int n_tiles = (n_boxes + TILE - 1) / TILE;

    cudaFuncSetAttribute(iou_kernel, cudaFuncAttributeMaxDynamicSharedMemorySize,
                         SMEM_BYTES);

    int grid = 152 * 3;               // persistent: 3 blocks/SM (75.8KB dyn smem each)
    if (grid > n_tiles) grid = n_tiles;
    iou_kernel<<<grid, THREADS, SMEM_BYTES>>>(cell, outp, tgt, res, n_boxes, n_tiles);
}

// round 16
// speedup vs baseline: 1.1325x; 1.0044x over previous
#include <cuda_runtime.h>
#include <cuda_bf16.h>

// IoU_31336081391713: elementwise YOLO IoU.
// Inputs: cell_nos [N,2] i32, output [N,5,5] f32, target [N,5] f32 -> IoU [N,5] f32.
// R15: fully-async DMA pipeline. Loads = 3x cp.async.bulk per tile completing on
// an mbarrier (warps HW-sleep); stores = 1x cp.async.bulk per tile (R12). The SM
// issues ~10 memory-machinery instructions per tile instead of ~2400 LDGSTS.

#define YI 20.0f
#define TILE 256          // boxes per tile == threads per block
#define THREADS 256
#define NA 5
#define OUT_F (TILE * 25) // 6400 floats (25600 B)
#define TGT_F (TILE * 5)  // 1280 floats (5120 B)
#define CELL_I (TILE * 2) // 512 ints   (2048 B)
#define STAGE_BYTES (OUT_F * 4 + TGT_F * 4 + CELL_I * 4)  // 32768

// dynamic smem layout (bytes)
#define OFF_OUT0 0
#define OFF_OUT1 (OFF_OUT0 + OUT_F * 4)
#define OFF_TGT0 (OFF_OUT1 + OUT_F * 4)
#define OFF_TGT1 (OFF_TGT0 + TGT_F * 4)
#define OFF_CEL0 (OFF_TGT1 + TGT_F * 4)
#define OFF_CEL1 (OFF_CEL0 + CELL_I * 4)
#define OFF_RES0 (OFF_CEL1 + CELL_I * 4)
#define OFF_RES1 (OFF_RES0 + TGT_F * 4)
#define OFF_MBAR (OFF_RES1 + TGT_F * 4)     // 2 x 8B mbarriers
#define SMEM_BYTES (OFF_MBAR + 16)          // 75792 B -> 3 blocks/SM

__device__ __forceinline__ unsigned s2u(const void* p) {
    return (unsigned)__cvta_generic_to_shared(p);
}
__device__ __forceinline__ void bulk_load(void* smem, const void* gmem,
                                          unsigned bytes, unsigned mbar) {
    asm volatile(
        "cp.async.bulk.shared::cta.global.mbarrier::complete_tx::bytes "
        "[%0], [%1], %2, [%3];\n"
        :: "r"(s2u(smem)), "l"(gmem), "r"(bytes), "r"(mbar) : "memory");
}
__device__ __forceinline__ void bulk_store(void* gmem, const void* smem, unsigned bytes) {
    asm volatile("cp.async.bulk.global.shared::cta.bulk_group [%0], [%1], %2;\n"
                 :: "l"(gmem), "r"(s2u(smem)), "r"(bytes) : "memory");
}
#define BULK_COMMIT()     asm volatile("cp.async.bulk.commit_group;\n" ::: "memory")
#define BULK_WAIT_READ1() asm volatile("cp.async.bulk.wait_group.read 1;\n" ::: "memory")
#define BULK_WAIT0()      asm volatile("cp.async.bulk.wait_group 0;\n" ::: "memory")
#define FENCE_ASYNC()     asm volatile("fence.proxy.async.shared::cta;\n" ::: "memory")

__device__ __forceinline__ void mbar_init(unsigned mbar, unsigned count) {
    asm volatile("mbarrier.init.shared.b64 [%0], %1;\n" :: "r"(mbar), "r"(count) : "memory");
}
__device__ __forceinline__ void mbar_expect_tx(unsigned mbar, unsigned bytes) {
    asm volatile("mbarrier.arrive.expect_tx.shared.b64 _, [%0], %1;\n"
                 :: "r"(mbar), "r"(bytes) : "memory");
}
__device__ __forceinline__ void mbar_wait(unsigned mbar, unsigned parity) {
    asm volatile(
        "{\n\t.reg .pred P;\n\t"
        "WAIT_%=:\n\t"
        "mbarrier.try_wait.parity.acquire.cta.shared::cta.b64 P, [%0], %1, 0x989680;\n\t"
        "@P bra DONE_%=;\n\t"
        "bra WAIT_%=;\n\t"
        "DONE_%=:\n\t}"
        :: "r"(mbar), "r"(parity) : "memory");
}

// tid0 issues the 3 DMA loads for tile `b0` into stage `st` (full tiles only).
__device__ __forceinline__ void issue_loads(
    char* base, int st, size_t b0, unsigned mbar,
    const int* __restrict__ g_cell,
    const float* __restrict__ g_out,
    const float* __restrict__ g_tgt)
{
    mbar_expect_tx(mbar, STAGE_BYTES);
    bulk_load(base + (st ? OFF_OUT1 : OFF_OUT0), g_out + b0 * 25, OUT_F * 4, mbar);
    bulk_load(base + (st ? OFF_TGT1 : OFF_TGT0), g_tgt + b0 * 5, TGT_F * 4, mbar);
    bulk_load(base + (st ? OFF_CEL1 : OFF_CEL0), g_cell + b0 * 2, CELL_I * 4, mbar);
}

__global__ __launch_bounds__(THREADS) void iou_kernel(
    const int*   __restrict__ g_cell,
    const float* __restrict__ g_out,
    const float* __restrict__ g_tgt,
    float*       __restrict__ g_res,
    int n_boxes, int n_tiles, int n_full_tiles)
{
    extern __shared__ char base[];
    const unsigned mb0 = s2u(base + OFF_MBAR);
    const unsigned mb1 = mb0 + 8;

    const int tid = threadIdx.x;
    const int G   = gridDim.x;

    // init mbarriers (count=1: only tid0's expect_tx arrive) and publish to async proxy
    if (tid == 0) {
        mbar_init(mb0, 1);
        mbar_init(mb1, 1);
        FENCE_ASYNC();
    }
    __syncthreads();

    // prologue: DMA first tile into stage 0
    if (tid == 0 && blockIdx.x < n_full_tiles) {
        issue_loads(base, 0, (size_t)blockIdx.x * TILE, mb0, g_cell, g_out, g_tgt);
    }

    int st = 0, rb = 0;
    unsigned ph0 = 0, ph1 = 0;   // consumer phase per stage
    for (int it = blockIdx.x; it < n_tiles; it += G, st ^= 1, rb ^= 1) {
        // issue DMA for tile it+G into the other stage (overlaps everything).
        // Reuse-safe: stage st^1's readers finished at the previous iteration's
        // trailing __syncthreads, which tid0 also passed.
        const int nt = it + G;
        if (tid == 0 && nt < n_full_tiles) {
            issue_loads(base, st ^ 1, (size_t)nt * TILE, st ? mb0 : mb1,
                        g_cell, g_out, g_tgt);
        }

        const size_t b0 = (size_t)it * TILE;
        const bool fullt = (it < n_full_tiles);
        int nb = n_boxes - (int)b0; if (nb > TILE) nb = TILE;

        if (fullt) {
            // all threads sleep on this stage's mbarrier (acquire -> smem reads ok)
            if (st == 0) { mbar_wait(mb0, ph0); ph0 ^= 1; }
            else         { mbar_wait(mb1, ph1); ph1 ^= 1; }
        }
        if (tid == 0) BULK_WAIT_READ1();   // s_res[rb] drained by bulk engine
        __syncthreads();                    // broadcast s_res reuse safety

        float* s_res = (float*)(base + (rb ? OFF_RES1 : OFF_RES0));

        if (tid < nb) {
            float ci, cj, t1, t2, t3, t4;
            const float* o;
            float og[20];
            if (fullt) {
                const int*   s_cel = (const int*)  (base + (st ? OFF_CEL1 : OFF_CEL0));
                const float* s_tgt = (const float*)(base + (st ? OFF_TGT1 : OFF_TGT0));
                const float* s_out = (const float*)(base + (st ? OFF_OUT1 : OFF_OUT0));
                ci = (float)s_cel[tid * 2 + 0] * YI + YI * 0.5f;
                cj = (float)s_cel[tid * 2 + 1] * YI + YI * 0.5f;
                const float* t = &s_tgt[tid * 5];
                t1 = t[1]; t2 = t[2]; t3 = t[3]; t4 = t[4];
                o = &s_out[tid * 25];
            } else {
                // tail: direct gmem path (dormant for N=4M)
                const size_t b = b0 + tid;
                ci = (float)g_cell[b * 2 + 0] * YI + YI * 0.5f;
                cj = (float)g_cell[b * 2 + 1] * YI + YI * 0.5f;
                t1 = g_tgt[b * 5 + 1]; t2 = g_tgt[b * 5 + 2];
                t3 = g_tgt[b * 5 + 3]; t4 = g_tgt[b * 5 + 4];
                #pragma unroll
                for (int a = 0; a < NA; a++) {
                    og[a * 4 + 0] = g_out[b * 25 + a * 5 + 1];
                    og[a * 4 + 1] = g_out[b * 25 + a * 5 + 2];
                    og[a * 4 + 2] = g_out[b * 25 + a * 5 + 3];
                    og[a * 4 + 3] = g_out[b * 25 + a * 5 + 4];
                }
                o = nullptr;
            }

            const float hg  = t3 * YI;
            const float wg  = t4 * YI;
            const float xcg = ci + t1 * YI;
            const float ycg = cj + t2 * YI;
            const float gx1 = ycg - wg * 0.5f;
            const float gy1 = xcg - hg * 0.5f;
            const float gx2 = ycg + wg * 0.5f;
            const float gy2 = xcg + hg * 0.5f;
            const float area_g = (gx2 - gx1) * (gy2 - gy1);

            #pragma unroll
            for (int a = 0; a < NA; a++) {
                float p1, p2, p3, p4;
                if (o) { p1 = o[a*5+1]; p2 = o[a*5+2]; p3 = o[a*5+3]; p4 = o[a*5+4]; }
                else   { p1 = og[a*4];  p2 = og[a*4+1]; p3 = og[a*4+2]; p4 = og[a*4+3]; }
                const float h  = p3 * YI;
                const float w  = p4 * YI;
                const float xc = ci + p1 * YI;
                const float yc = cj + p2 * YI;
                const float px1 = yc - w * 0.5f;
                const float py1 = xc - h * 0.5f;
                const float px2 = yc + w * 0.5f;
                const float py2 = xc + h * 0.5f;
                const float area_p = (px2 - px1) * (py2 - py1);

                const float ltx = fmaxf(px1, gx1);
                const float lty = fmaxf(py1, gy1);
                const float rbx = fminf(px2, gx2);
                const float rby = fminf(py2, gy2);
                const float wx  = fmaxf(rbx - ltx, 0.0f);
                const float wy  = fmaxf(rby - lty, 0.0f);
                const float inter = wx * wy;
                const float uni   = area_p + area_g - inter;
                if (fullt) s_res[tid * 5 + a] = inter / uni;
                else       g_res[(b0 + tid) * 5 + a] = inter / uni;
            }
        }
        __syncthreads();          // s_res complete; also gates next stage re-issue

        if (fullt) {
            if (tid == 0) {
                FENCE_ASYNC();    // order generic s_res writes into async proxy
                bulk_store(g_res + b0 * 5, s_res, (unsigned)(TGT_F * 4));  // 5120B
                BULK_COMMIT();
            }
        }
    }

    if (tid == 0) BULK_WAIT0();   // all bulk stores complete before exit
}

extern "C" void kernel_launch(void* const* d_in, const int* in_sizes, int n_in,
                              void* d_out, int out_size) {
    const int*   cell = (const int*)d_in[0];
    const float* outp = (const float*)d_in[1];
    const float* tgt  = (const float*)d_in[2];
    float*       res  = (float*)d_out;

    const int n_boxes = in_sizes[0] / 2;
    const int n_tiles = (n_boxes + TILE - 1) / TILE;
    const int n_full_tiles = n_boxes / TILE;

    cudaFuncSetAttribute(iou_kernel, cudaFuncAttributeMaxDynamicSharedMemorySize,
                         SMEM_BYTES);

    int grid = 152 * 3;               // persistent: 3 blocks/SM (75.8KB dyn smem each)
    if (grid > n_tiles) grid = n_tiles;
    iou_kernel<<<grid, THREADS, SMEM_BYTES>>>(cell, outp, tgt, res,
                                              n_boxes, n_tiles, n_full_tiles);
}